// round 3
// baseline (speedup 1.0000x reference)
#include <cuda_runtime.h>
#include <math.h>

#define Bn 32
#define Sn 512
#define Hn 768
#define FDn 64
#define Pn 30
#define NROWS (Bn*Sn)    // 16384

typedef unsigned long long u64;

__device__ __forceinline__ void fma2(u64 &d, u64 a, u64 b) {
    asm("fma.rn.f32x2 %0, %1, %2, %0;" : "+l"(d) : "l"(a), "l"(b));
}
__device__ __forceinline__ void add2(u64 &d, u64 a) {
    asm("add.rn.f32x2 %0, %0, %1;" : "+l"(d) : "l"(a));
}
__device__ __forceinline__ u64 rep2(float a) {
    u64 r; asm("mov.b64 %0, {%1, %1};" : "=l"(r) : "f"(a)); return r;
}
__device__ __forceinline__ float2 unpk(u64 v) {
    float2 f; asm("mov.b64 {%0, %1}, %2;" : "=f"(f.x), "=f"(f.y) : "l"(v)); return f;
}

// ------------------ scratch ------------------
__device__ float g_WT [Hn * 32];          // W_t^T [k][p] (p padded to 32)
__device__ float g_WaT[FDn * 32];         // W_a^T [k][p]
__device__ float g_pt [8 * NROWS * 32];   // text partials [ks][row][p]  (16.8 MB)
__device__ float g_textT [Bn * 32 * Sn];  // [b][p][s]
__device__ float g_audioT[Bn * 32 * Sn];  // [b][p][s]
__device__ float g_part[128];
__device__ float g_scale[1];
__device__ float g_raw0[Bn * Sn];
__device__ float g_prob[Bn * Sn];
__device__ float g_avp[Bn * 16 * Hn];
__device__ float g_h[Bn * Hn];

// ------------------ K0: transpose weights ------------------
__global__ void k_prep(const float* __restrict__ Wt, const float* __restrict__ Wa) {
    int e = blockIdx.x * 256 + threadIdx.x;
    if (blockIdx.x < 96) {
        int p = e & 31, k = e >> 5;
        g_WT[k * 32 + p] = (p < Pn) ? Wt[p * Hn + k] : 0.f;
    } else {
        e -= 96 * 256;
        int p = e & 31, k = e >> 5;
        g_WaT[k * 32 + p] = (p < Pn) ? Wa[p * FDn + k] : 0.f;
    }
}

// ------------------ K1: text projection, K-split, 8x8 micro, f32x2 ------------------
// grid (64 row-tiles of 256, 8 k-splits of 96), block 128 = 32 rthr x 4 pthr
__global__ __launch_bounds__(128) void k_proj(const float* __restrict__ hs) {
    __shared__ float sA[256 * 17];   // chunk 256 rows x 16 k, pitch 17
    __shared__ float sW[16 * 32];
    int tid = threadIdx.x;
    int rthr = tid >> 2, pthr = tid & 3;
    int row0 = blockIdx.x * 256;
    int kbase = blockIdx.y * 96;

    u64 acc[8][4];
    #pragma unroll
    for (int i = 0; i < 8; i++)
        #pragma unroll
        for (int j = 0; j < 4; j++) acc[i][j] = 0ull;

    for (int cc = 0; cc < 6; cc++) {
        int kb = kbase + cc * 16;
        __syncthreads();
        #pragma unroll
        for (int q = 0; q < 8; q++) {           // A: 256x16 = 1024 float4
            int e = tid + 128 * q;
            int r = e >> 2, k4 = e & 3;
            float4 v = ((const float4*)hs)[(size_t)(row0 + r) * 192 + (kb >> 2) + k4];
            float* d = &sA[r * 17 + k4 * 4];
            d[0] = v.x; d[1] = v.y; d[2] = v.z; d[3] = v.w;
        }
        {                                        // W: 16x32 = 128 float4
            int k = tid >> 3, p4 = tid & 7;
            float4 v = ((const float4*)g_WT)[(kb + k) * 8 + p4];
            *(float4*)&sW[k * 32 + p4 * 4] = v;
        }
        __syncthreads();
        #pragma unroll
        for (int k = 0; k < 16; k++) {
            u64 w[4];
            #pragma unroll
            for (int j = 0; j < 4; j++)
                w[j] = *(const u64*)&sW[k * 32 + pthr * 8 + 2 * j];
            #pragma unroll
            for (int i = 0; i < 8; i++) {
                u64 a = rep2(sA[(rthr * 8 + i) * 17 + k]);
                fma2(acc[i][0], a, w[0]);
                fma2(acc[i][1], a, w[1]);
                fma2(acc[i][2], a, w[2]);
                fma2(acc[i][3], a, w[3]);
            }
        }
    }
    // store partials
    #pragma unroll
    for (int i = 0; i < 8; i++) {
        size_t base = (size_t)blockIdx.y * (NROWS * 32) +
                      (size_t)(row0 + rthr * 8 + i) * 32 + pthr * 8;
        u64* d = (u64*)&g_pt[base];
        d[0] = acc[i][0]; d[1] = acc[i][1]; d[2] = acc[i][2]; d[3] = acc[i][3];
    }
}

// ------------------ K1b: finalize = sum partials + audio GEMM + transpose ------------------
// grid 128 (128-row tiles), block 128 = 32 rthr x 4 pthr, micro 4r x 8p
__global__ __launch_bounds__(128) void k_fin(const float* __restrict__ ad) {
    __shared__ float sbuf[128 * 68 + 64 * 32];   // audio tile + Wa; reused for transpose
    __shared__ float red[128];
    float* sAa = sbuf;                // 128 x 64, pitch 68
    float* sWa = sbuf + 128 * 68;     // 64 x 32
    float* sX  = sbuf;                // transpose buffer 32 x 129 (alias)

    int tid = threadIdx.x;
    int rthr = tid >> 2, pthr = tid & 3;
    int row0 = blockIdx.x * 128;
    int b = row0 >> 9, sbase = row0 & 511;

    // load audio tile + weights
    #pragma unroll
    for (int q = 0; q < 16; q++) {               // 128 rows x 16 float4
        int e = tid + 128 * q;
        int r = e >> 4, c = e & 15;
        float4 v = ((const float4*)ad)[(size_t)(row0 + r) * 16 + c];
        *(float4*)&sAa[r * 68 + c * 4] = v;
    }
    #pragma unroll
    for (int q = 0; q < 4; q++) {                // 64x32 = 512 float4
        int e = tid + 128 * q;
        int k = e >> 3, p4 = e & 7;
        float4 v = ((const float4*)g_WaT)[k * 8 + p4];
        *(float4*)&sWa[k * 32 + p4 * 4] = v;
    }
    __syncthreads();

    // audio GEMM
    u64 aacc[4][4];
    #pragma unroll
    for (int i = 0; i < 4; i++)
        #pragma unroll
        for (int j = 0; j < 4; j++) aacc[i][j] = 0ull;
    #pragma unroll 8
    for (int k = 0; k < 64; k++) {
        u64 w[4];
        #pragma unroll
        for (int j = 0; j < 4; j++)
            w[j] = *(const u64*)&sWa[k * 32 + pthr * 8 + 2 * j];
        #pragma unroll
        for (int i = 0; i < 4; i++) {
            u64 a = rep2(sAa[(rthr * 4 + i) * 68 + k]);
            fma2(aacc[i][0], a, w[0]);
            fma2(aacc[i][1], a, w[1]);
            fma2(aacc[i][2], a, w[2]);
            fma2(aacc[i][3], a, w[3]);
        }
    }

    // text partial sums (gmem, no smem needed)
    u64 tacc[4][4];
    #pragma unroll
    for (int i = 0; i < 4; i++) {
        size_t base = (size_t)(row0 + rthr * 4 + i) * 32 + pthr * 8;
        #pragma unroll
        for (int j = 0; j < 4; j++) tacc[i][j] = 0ull;
        #pragma unroll
        for (int ks = 0; ks < 8; ks++) {
            const u64* s = (const u64*)&g_pt[(size_t)ks * (NROWS * 32) + base];
            add2(tacc[i][0], s[0]); add2(tacc[i][1], s[1]);
            add2(tacc[i][2], s[2]); add2(tacc[i][3], s[3]);
        }
    }

    // sumsq
    float sumsq = 0.f;
    #pragma unroll
    for (int i = 0; i < 4; i++)
        #pragma unroll
        for (int j = 0; j < 4; j++) {
            float2 f = unpk(tacc[i][j]);
            sumsq += f.x * f.x + f.y * f.y;
        }
    red[tid] = sumsq;

    // transpose text via smem, then coalesced store
    __syncthreads();
    #pragma unroll
    for (int i = 0; i < 4; i++)
        #pragma unroll
        for (int j = 0; j < 4; j++) {
            float2 f = unpk(tacc[i][j]);
            int s = rthr * 4 + i;
            sX[(pthr * 8 + 2 * j)     * 129 + s] = f.x;
            sX[(pthr * 8 + 2 * j + 1) * 129 + s] = f.y;
        }
    __syncthreads();
    #pragma unroll
    for (int q = 0; q < 32; q++) {
        int e = tid + 128 * q;                   // 4096
        int p = e >> 7, c = e & 127;
        g_textT[(size_t)(b * 32 + p) * 512 + sbase + c] = sX[p * 129 + c];
    }
    __syncthreads();
    // transpose audio
    #pragma unroll
    for (int i = 0; i < 4; i++)
        #pragma unroll
        for (int j = 0; j < 4; j++) {
            float2 f = unpk(aacc[i][j]);
            int s = rthr * 4 + i;
            sX[(pthr * 8 + 2 * j)     * 129 + s] = f.x;
            sX[(pthr * 8 + 2 * j + 1) * 129 + s] = f.y;
        }
    __syncthreads();
    #pragma unroll
    for (int q = 0; q < 32; q++) {
        int e = tid + 128 * q;
        int p = e >> 7, c = e & 127;
        g_audioT[(size_t)(b * 32 + p) * 512 + sbase + c] = sX[p * 129 + c];
    }

    // reduce sumsq
    __syncthreads();
    for (int s = 64; s > 0; s >>= 1) {
        if (tid < s) red[tid] += red[tid + s];
        __syncthreads();
    }
    if (tid == 0) g_part[blockIdx.x] = red[0];
}

// ------------------ K2: norm scale ------------------
__global__ void k_norm() {
    __shared__ float red[128];
    int tid = threadIdx.x;
    red[tid] = g_part[tid];
    __syncthreads();
    for (int s = 64; s > 0; s >>= 1) {
        if (tid < s) red[tid] += red[tid + s];
        __syncthreads();
    }
    if (tid == 0) g_scale[0] = rsqrtf(red[0]);
}

// ------------------ K3: scores, warp-specialized, 8x8 micro, f32x2 ------------------
// grid (36 tri-tiles, 32 b), block 128 = 4 warps (2 text, 2 audio)
__global__ __launch_bounds__(128) void k_scores(const float* __restrict__ twp,
                                                const float* __restrict__ awp,
                                                const float* __restrict__ fbp,
                                                float* __restrict__ out_ta,
                                                float* __restrict__ out_fa) {
    __shared__ float tiles[4 * 32 * 64];     // sSt, sTt, sSa, sTa (8 KB each)
    float* sSt = tiles;
    float* sTt = tiles + 2048;
    float* sSa = tiles + 4096;
    float* sTa = tiles + 6144;
    float* xch = tiles;                      // 64 x 65 alias (after compute)

    int x = blockIdx.x, si = 0;
    while (x >= 8 - si) { x -= 8 - si; si++; }
    int ti = si + x;
    int b = blockIdx.y;
    int s0 = si * 64, t0 = ti * 64;
    int tid = threadIdx.x, warp = tid >> 5, lane = tid & 31;
    int m = warp >> 1;                        // 0 text, 1 audio
    int idx = ((warp & 1) << 5) | lane;       // 0..63
    int sthr = idx >> 3, tthr = idx & 7;

    const float4* gT = (const float4*)(g_textT  + (size_t)b * 32 * 512);
    const float4* gA = (const float4*)(g_audioT + (size_t)b * 32 * 512);
    #pragma unroll
    for (int q = 0; q < 4; q++) {
        int e = tid + 128 * q;                // 512 float4 per tile
        int p = e >> 4, c = e & 15;
        ((float4*)sSt)[p * 16 + c] = gT[p * 128 + (s0 >> 2) + c];
        ((float4*)sTt)[p * 16 + c] = gT[p * 128 + (t0 >> 2) + c];
        ((float4*)sSa)[p * 16 + c] = gA[p * 128 + (s0 >> 2) + c];
        ((float4*)sTa)[p * 16 + c] = gA[p * 128 + (t0 >> 2) + c];
    }
    __syncthreads();

    const float* sS = m ? sSa : sSt;
    const float* sT = m ? sTa : sTt;
    u64 acc[8][4];
    #pragma unroll
    for (int i = 0; i < 8; i++)
        #pragma unroll
        for (int j = 0; j < 4; j++) acc[i][j] = 0ull;

    #pragma unroll 5
    for (int p = 0; p < Pn; p++) {
        const float* ps = sS + p * 64 + sthr * 8;
        const float* pt = sT + p * 64 + tthr * 8;
        u64 t0v = *(const u64*)(pt);
        u64 t1v = *(const u64*)(pt + 2);
        u64 t2v = *(const u64*)(pt + 4);
        u64 t3v = *(const u64*)(pt + 6);
        #pragma unroll
        for (int i = 0; i < 8; i++) {
            u64 a = rep2(ps[i]);
            fma2(acc[i][0], a, t0v);
            fma2(acc[i][1], a, t1v);
            fma2(acc[i][2], a, t2v);
            fma2(acc[i][3], a, t3v);
        }
    }
    __syncthreads();   // everyone done reading tiles

    if (m == 1) {
        // audio warps: relu and write to exchange buffer [s][t] pitch 65
        #pragma unroll
        for (int i = 0; i < 8; i++) {
            float* row = xch + (sthr * 8 + i) * 65 + tthr * 8;
            #pragma unroll
            for (int j = 0; j < 4; j++) {
                float2 f = unpk(acc[i][j]);
                row[2 * j]     = fmaxf(f.x, 0.f);
                row[2 * j + 1] = fmaxf(f.y, 0.f);
            }
        }
    }
    float cs = g_scale[0];
    float tw = twp[0], aw = awp[0], fb = fbp[0];
    float tav[8][8];
    if (m == 0) {
        #pragma unroll
        for (int i = 0; i < 8; i++)
            #pragma unroll
            for (int j = 0; j < 4; j++) {
                float2 f = unpk(acc[i][j]);
                tav[i][2 * j]     = fmaxf(f.x * cs, 0.f);
                tav[i][2 * j + 1] = fmaxf(f.y * cs, 0.f);
            }
    }
    __syncthreads();

    if (m == 0) {
        // normal stores [s][t]
        #pragma unroll
        for (int i = 0; i < 8; i++) {
            int s = s0 + sthr * 8 + i;
            const float* arow = xch + (sthr * 8 + i) * 65 + tthr * 8;
            size_t base = ((size_t)(b * Sn + s)) * Sn + t0 + tthr * 8;
            float fa[8], rw[8];
            #pragma unroll
            for (int j = 0; j < 8; j++) {
                float r_ = tw * tav[i][j] + aw * arow[j] + fb;
                rw[j] = r_;
                fa[j] = fmaxf(r_, 0.f);
            }
            *(float4*)(out_ta + base)     = make_float4(tav[i][0], tav[i][1], tav[i][2], tav[i][3]);
            *(float4*)(out_ta + base + 4) = make_float4(tav[i][4], tav[i][5], tav[i][6], tav[i][7]);
            *(float4*)(out_fa + base)     = make_float4(fa[0], fa[1], fa[2], fa[3]);
            *(float4*)(out_fa + base + 4) = make_float4(fa[4], fa[5], fa[6], fa[7]);
            if (si == 0 && sthr == 0 && i == 0) {
                *(float4*)(g_raw0 + b * Sn + t0 + tthr * 8)     = make_float4(rw[0], rw[1], rw[2], rw[3]);
                *(float4*)(g_raw0 + b * Sn + t0 + tthr * 8 + 4) = make_float4(rw[4], rw[5], rw[6], rw[7]);
            }
        }
        // mirror stores [t][s] (recompute fa from xch column)
        if (si != ti) {
            #pragma unroll
            for (int j = 0; j < 8; j++) {
                int t = t0 + tthr * 8 + j;
                size_t base = ((size_t)(b * Sn + t)) * Sn + s0 + sthr * 8;
                float fa[8];
                #pragma unroll
                for (int i = 0; i < 8; i++) {
                    float a_ = xch[(sthr * 8 + i) * 65 + tthr * 8 + j];
                    fa[i] = fmaxf(tw * tav[i][j] + aw * a_ + fb, 0.f);
                }
                *(float4*)(out_ta + base)     = make_float4(tav[0][j], tav[1][j], tav[2][j], tav[3][j]);
                *(float4*)(out_ta + base + 4) = make_float4(tav[4][j], tav[5][j], tav[6][j], tav[7][j]);
                *(float4*)(out_fa + base)     = make_float4(fa[0], fa[1], fa[2], fa[3]);
                *(float4*)(out_fa + base + 4) = make_float4(fa[4], fa[5], fa[6], fa[7]);
            }
        }
    }
}

// ------------------ K4: softmax probs for s=0 row ------------------
__global__ __launch_bounds__(256) void k_soft(const float* __restrict__ am) {
    __shared__ float red[256];
    int b = blockIdx.x, tid = threadIdx.x;
    float mbase = am[b * Sn];
    float l0 = g_raw0[b * Sn + tid]       + am[b * Sn + tid]       + mbase;
    float l1 = g_raw0[b * Sn + tid + 256] + am[b * Sn + tid + 256] + mbase;

    red[tid] = fmaxf(l0, l1);
    __syncthreads();
    for (int s = 128; s > 0; s >>= 1) {
        if (tid < s) red[tid] = fmaxf(red[tid], red[tid + s]);
        __syncthreads();
    }
    float mx = red[0];
    __syncthreads();
    float e0 = expf(l0 - mx), e1 = expf(l1 - mx);
    red[tid] = e0 + e1;
    __syncthreads();
    for (int s = 128; s > 0; s >>= 1) {
        if (tid < s) red[tid] += red[tid + s];
        __syncthreads();
    }
    float inv = 1.f / red[0];
    g_prob[b * Sn + tid]       = e0 * inv;
    g_prob[b * Sn + tid + 256] = e1 * inv;
}

// ------------------ K5: att @ hidden (t-split partials) ------------------
__global__ __launch_bounds__(192) void k_av(const float* __restrict__ hs) {
    __shared__ float sp[32];
    int b = blockIdx.x, cy = blockIdx.y, tid = threadIdx.x;
    int t0 = cy * 32;
    if (tid < 32) sp[tid] = g_prob[b * Sn + t0 + tid];
    __syncthreads();

    const float4* hb = (const float4*)(hs + (size_t)b * Sn * Hn);
    float4 acc = make_float4(0.f, 0.f, 0.f, 0.f);
    #pragma unroll 4
    for (int t = 0; t < 32; t++) {
        float p = sp[t];
        float4 h = hb[(size_t)(t0 + t) * 192 + tid];
        acc.x += p * h.x; acc.y += p * h.y; acc.z += p * h.z; acc.w += p * h.w;
    }
    ((float4*)g_avp)[(size_t)(b * 16 + cy) * 192 + tid] = acc;
}

// ------------------ K6: dense GEMV ------------------
__global__ __launch_bounds__(256) void k_dense(const float* __restrict__ hs,
                                               const float* __restrict__ Wd,
                                               const float* __restrict__ bd) {
    __shared__ float sx[Hn];
    int b = blockIdx.x, oc = blockIdx.y, tid = threadIdx.x;
    int w = tid >> 5, lane = tid & 31;

    for (int i = tid; i < Hn; i += 256) {
        float v = hs[(size_t)b * Sn * Hn + i];
        #pragma unroll
        for (int c = 0; c < 16; c++) v += g_avp[(size_t)(b * 16 + c) * Hn + i];
        sx[i] = v;
    }
    __syncthreads();

    const float4* sx4 = (const float4*)sx;
    #pragma unroll
    for (int q = 0; q < 12; q++) {
        int o = oc * 96 + w * 12 + q;
        const float4* w4 = (const float4*)(Wd + (size_t)o * Hn);
        float acc = 0.f;
        #pragma unroll
        for (int c = 0; c < 6; c++) {
            float4 wv = w4[c * 32 + lane];
            float4 xv = sx4[c * 32 + lane];
            acc += wv.x * xv.x + wv.y * xv.y + wv.z * xv.z + wv.w * xv.w;
        }
        #pragma unroll
        for (int s = 16; s > 0; s >>= 1)
            acc += __shfl_down_sync(0xffffffff, acc, s);
        if (lane == 0) g_h[b * Hn + o] = acc + bd[o];
    }
}

// ------------------ K7: layernorm ------------------
__global__ __launch_bounds__(256) void k_ln(const float* __restrict__ lw,
                                            const float* __restrict__ lb,
                                            float* __restrict__ out0) {
    __shared__ float red[256];
    int b = blockIdx.x, tid = threadIdx.x;
    float hv[3];
    #pragma unroll
    for (int j = 0; j < 3; j++) hv[j] = g_h[b * Hn + tid + 256 * j];

    red[tid] = hv[0] + hv[1] + hv[2];
    __syncthreads();
    for (int s = 128; s > 0; s >>= 1) {
        if (tid < s) red[tid] += red[tid + s];
        __syncthreads();
    }
    float u = red[0] / (float)Hn;
    __syncthreads();
    float vs = 0.f;
    #pragma unroll
    for (int j = 0; j < 3; j++) { float d = hv[j] - u; vs += d * d; }
    red[tid] = vs;
    __syncthreads();
    for (int s = 128; s > 0; s >>= 1) {
        if (tid < s) red[tid] += red[tid + s];
        __syncthreads();
    }
    float rstd = rsqrtf(red[0] / (float)Hn + 1e-12f);
    #pragma unroll
    for (int j = 0; j < 3; j++) {
        int o = tid + 256 * j;
        out0[b * Hn + o] = lw[o] * (hv[j] - u) * rstd + lb[o];
    }
}

// ------------------ launch ------------------
extern "C" void kernel_launch(void* const* d_in, const int* in_sizes, int n_in,
                              void* d_out, int out_size) {
    const float* hs = (const float*)d_in[0];
    const float* ad = (const float*)d_in[1];
    const float* am = (const float*)d_in[2];
    const float* Wt = (const float*)d_in[3];
    const float* Wa = (const float*)d_in[4];
    const float* tw = (const float*)d_in[5];
    const float* aw = (const float*)d_in[6];
    const float* fb = (const float*)d_in[7];
    const float* Wd = (const float*)d_in[8];
    const float* bd = (const float*)d_in[9];
    const float* lw = (const float*)d_in[10];
    const float* lb = (const float*)d_in[11];

    float* out    = (float*)d_out;
    float* out_h0 = out;
    float* out_ta = out + Bn * Hn;
    float* out_fa = out + Bn * Hn + (size_t)Bn * Sn * Sn;

    k_prep<<<104, 256>>>(Wt, Wa);
    k_proj<<<dim3(64, 8), 128>>>(hs);
    k_fin<<<128, 128>>>(ad);
    k_norm<<<1, 128>>>();
    k_scores<<<dim3(36, 32), 128>>>(tw, aw, fb, out_ta, out_fa);
    k_soft<<<32, 256>>>(am);
    k_av<<<dim3(32, 16), 192>>>(hs);
    k_dense<<<dim3(32, 8), 256>>>(hs, Wd, bd);
    k_ln<<<32, 256>>>(lw, lb, out_h0);
}